// round 14
// baseline (speedup 1.0000x reference)
#include <cuda_runtime.h>
#include <cuda_bf16.h>
#include <mma.h>
#include <math.h>
#include <stdint.h>

using namespace nvcuda;

#define NN 8192
#define DD 256
#define EE 262144
#define KK 8

// ---- arena layout inside Z region of d_out (16,777,216 floats) ----
#define S_DEG   0
#define S_OFF   8192
#define S_CUR   16384
#define S_ESRC  24576
#define S_EW    286720
#define S_WSP   548864
#define S_HCH   1048576
#define S_HCL   3145728
#define S_H1    5242880
#define S_E2H   7340032
#define S_E2L   8388608
#define S_ZLH   9437184
#define S_KLP   10485760
#define S_GLP   10486016

// protected Z row-blocks: [256,512) and [3584,5248)
__device__ __forceinline__ bool row_protected(int rowBase) {
    return (rowBase >= 256 && rowBase < 512) || (rowBase >= 3584 && rowBase < 5248);
}

#define W1H 0
#define W1L 131072
#define W2H 262144
#define W2L 393216
#define W3H 524288
#define W3L 589824
#define W4H 655360
#define W4L 720896

#define HLDA 72
#define LDW 72
#define LDW2 136
#define LDC 72
#define LDCG 136
#define GW_SMEM  71680
#define HD_SMEM  73728
#define LDC2 132
#define LOSS_SMEM 69632
#define LDA 136
#define NLOSS 2080          // 64*65/2 triangular blocks

// ================= CSR build (4 edges/thread for atomic MLP) =================
__global__ void hist_kernel(const int* __restrict__ ei, int* deg) {
    int e4 = (blockIdx.x * 256 + threadIdx.x) * 4;
    int4 d = *(const int4*)(ei + EE + e4);
    atomicAdd(&deg[d.x], 1);
    atomicAdd(&deg[d.y], 1);
    atomicAdd(&deg[d.z], 1);
    atomicAdd(&deg[d.w], 1);
}
__global__ void scan_kernel(const int* __restrict__ deg, int* off, int* cur) {
    __shared__ int s[256];
    int tid = threadIdx.x;
    int base = tid * 32;
    int loc[32];
    int sum = 0;
#pragma unroll
    for (int i = 0; i < 32; i++) { loc[i] = deg[base + i]; sum += loc[i]; }
    s[tid] = sum;
    __syncthreads();
    for (int o = 1; o < 256; o <<= 1) {
        int v = (tid >= o) ? s[tid - o] : 0;
        __syncthreads();
        s[tid] += v;
        __syncthreads();
    }
    int run = s[tid] - sum;
#pragma unroll
    for (int i = 0; i < 32; i++) {
        off[base + i] = run;
        cur[base + i] = run;
        run += loc[i];
    }
}
__global__ void fill_kernel(const int* __restrict__ ei, const float* __restrict__ w,
                            int* cur, int* esrc, float* ew) {
    int e4 = (blockIdx.x * 256 + threadIdx.x) * 4;
    int4   s4 = *(const int4*)(ei + e4);
    int4   d4 = *(const int4*)(ei + EE + e4);
    float4 w4 = *(const float4*)(w + e4);
    int s0 = atomicAdd(&cur[d4.x], 1);
    int s1 = atomicAdd(&cur[d4.y], 1);
    int s2 = atomicAdd(&cur[d4.z], 1);
    int s3 = atomicAdd(&cur[d4.w], 1);
    esrc[s0] = s4.x; ew[s0] = w4.x;
    esrc[s1] = s4.y; ew[s1] = w4.y;
    esrc[s2] = s4.z; ew[s2] = w4.z;
    esrc[s3] = s4.w; ew[s3] = w4.w;
}

// ============ fused: zero deg + split all 4 weights ============
__global__ void split_w_all(const float* __restrict__ W1, const float* __restrict__ W2,
                            const float* __restrict__ W3, const float* __restrict__ W4,
                            __nv_bfloat16* __restrict__ wsp, int* __restrict__ deg) {
    int gid = blockIdx.x * 256 + threadIdx.x;
    if (gid < NN) deg[gid] = 0;
    int idx4 = gid * 4;
    const float* src;
    int local;
    __nv_bfloat16 *dh, *dl;
    if (idx4 < 131072)      { src = W1; local = idx4;          dh = wsp + W1H; dl = wsp + W1L; }
    else if (idx4 < 262144) { src = W2; local = idx4 - 131072; dh = wsp + W2H; dl = wsp + W2L; }
    else if (idx4 < 327680) { src = W3; local = idx4 - 262144; dh = wsp + W3H; dl = wsp + W3L; }
    else                    { src = W4; local = idx4 - 327680; dh = wsp + W4H; dl = wsp + W4L; }
    float4 v = *(const float4*)(src + local);
    __nv_bfloat16 h0 = __float2bfloat16(v.x), h1 = __float2bfloat16(v.y);
    __nv_bfloat16 h2 = __float2bfloat16(v.z), h3 = __float2bfloat16(v.w);
    *(__nv_bfloat162*)(dh + local)     = __nv_bfloat162(h0, h1);
    *(__nv_bfloat162*)(dh + local + 2) = __nv_bfloat162(h2, h3);
    *(__nv_bfloat162*)(dl + local) = __nv_bfloat162(
        __float2bfloat16(v.x - __bfloat162float(h0)),
        __float2bfloat16(v.y - __bfloat162float(h1)));
    *(__nv_bfloat162*)(dl + local + 2) = __nv_bfloat162(
        __float2bfloat16(v.z - __bfloat162float(h2)),
        __float2bfloat16(v.w - __bfloat162float(h3)));
}

// ============ gather conv + combine (4 independent accumulators) ============
__global__ void gather_kernel(const float* __restrict__ x,
                              __nv_bfloat16* __restrict__ hch,
                              __nv_bfloat16* __restrict__ hcl,
                              const int* __restrict__ deg, const int* __restrict__ off,
                              const int* __restrict__ esrc, const float* __restrict__ ew) {
    __shared__ int   ss[256];
    __shared__ float sw[256];
    int n = blockIdx.x, d = threadIdx.x;
    int beg = off[n];
    int dg  = deg[n];
    float a0 = 0.f, a1 = 0.f, a2 = 0.f, a3 = 0.f;
    for (int c = 0; c < dg; c += 256) {
        int m = min(256, dg - c);
        if (d < m) { ss[d] = esrc[beg + c + d]; sw[d] = ew[beg + c + d]; }
        __syncthreads();
        int j = 0;
        for (; j + 3 < m; j += 4) {
            a0 = fmaf(x[(size_t)ss[j + 0] * DD + d], sw[j + 0], a0);
            a1 = fmaf(x[(size_t)ss[j + 1] * DD + d], sw[j + 1], a1);
            a2 = fmaf(x[(size_t)ss[j + 2] * DD + d], sw[j + 2], a2);
            a3 = fmaf(x[(size_t)ss[j + 3] * DD + d], sw[j + 3], a3);
        }
        for (; j < m; j++)
            a0 = fmaf(x[(size_t)ss[j] * DD + d], sw[j], a0);
        __syncthreads();
    }
    float acc = (a0 + a1) + (a2 + a3);
    float xv = x[(size_t)n * DD + d];
    float av = acc / fmaxf((float)dg, 1.f);
    __nv_bfloat16 xh = __float2bfloat16(xv);
    __nv_bfloat16 ah = __float2bfloat16(av);
    int base = n * 512 + d;
    hch[base]       = xh;
    hch[base + 256] = ah;
    hcl[base]       = __float2bfloat16(xv - __bfloat162float(xh));
    hcl[base + 256] = __float2bfloat16(av - __bfloat162float(ah));
}

// ====== bf16 GEMM, N-tile 128, K-chunk 64 ======
template<bool RELU, bool RES, bool SPLITOUT, int KD>
__global__ void __launch_bounds__(256, 2) gemm_bf16(
    const __nv_bfloat16* __restrict__ Ahg, const __nv_bfloat16* __restrict__ Alg,
    const __nv_bfloat16* __restrict__ Whg, const __nv_bfloat16* __restrict__ Wlg,
    const float* __restrict__ bias, const float* __restrict__ res,
    float* __restrict__ C, __nv_bfloat16* __restrict__ Ch, __nv_bfloat16* __restrict__ Cl) {
    extern __shared__ __align__(16) char sm[];
    __nv_bfloat16* Ah = (__nv_bfloat16*)sm;
    __nv_bfloat16* Al = Ah + 128 * HLDA;
    __nv_bfloat16* Wh = Al + 128 * HLDA;
    __nv_bfloat16* Wl = Wh + 64 * LDW2;
    int tid = threadIdx.x, wid = tid >> 5;
    int wm0 = (wid & 3) * 32, wn0 = (wid >> 2) * 64;
    int rowBase = blockIdx.y * 128, colBase = blockIdx.x * 128;

    wmma::fragment<wmma::accumulator, 16, 16, 16, float> acc[2][4];
#pragma unroll
    for (int m = 0; m < 2; m++)
#pragma unroll
        for (int n = 0; n < 4; n++) wmma::fill_fragment(acc[m][n], 0.f);

    for (int kc = 0; kc < KD / 64; kc++) {
        int kg = kc * 64;
        for (int idx = tid; idx < 128 * 8; idx += 256) {
            int r = idx >> 3, c8 = (idx & 7) << 3;
            size_t g = (size_t)(rowBase + r) * KD + kg + c8;
            *(uint4*)&Ah[r * HLDA + c8] = *(const uint4*)(Ahg + g);
            *(uint4*)&Al[r * HLDA + c8] = *(const uint4*)(Alg + g);
        }
        for (int idx = tid; idx < 64 * 16; idx += 256) {
            int k = idx >> 4, c8 = (idx & 15) << 3;
            size_t g = (size_t)(kg + k) * 256 + colBase + c8;
            *(uint4*)&Wh[k * LDW2 + c8] = *(const uint4*)(Whg + g);
            *(uint4*)&Wl[k * LDW2 + c8] = *(const uint4*)(Wlg + g);
        }
        __syncthreads();
#pragma unroll
        for (int ks = 0; ks < 4; ks++) {
            int k0 = ks * 16;
            wmma::fragment<wmma::matrix_a, 16, 16, 16, __nv_bfloat16, wmma::row_major> aH[2], aL[2];
#pragma unroll
            for (int m = 0; m < 2; m++) {
                wmma::load_matrix_sync(aH[m], &Ah[(wm0 + m * 16) * HLDA + k0], HLDA);
                wmma::load_matrix_sync(aL[m], &Al[(wm0 + m * 16) * HLDA + k0], HLDA);
            }
#pragma unroll
            for (int n = 0; n < 4; n++) {
                wmma::fragment<wmma::matrix_b, 16, 16, 16, __nv_bfloat16, wmma::row_major> bH, bL;
                wmma::load_matrix_sync(bH, &Wh[k0 * LDW2 + wn0 + n * 16], LDW2);
                wmma::load_matrix_sync(bL, &Wl[k0 * LDW2 + wn0 + n * 16], LDW2);
#pragma unroll
                for (int m = 0; m < 2; m++) {
                    wmma::mma_sync(acc[m][n], aH[m], bH, acc[m][n]);
                    wmma::mma_sync(acc[m][n], aL[m], bH, acc[m][n]);
                    wmma::mma_sync(acc[m][n], aH[m], bL, acc[m][n]);
                }
            }
        }
        __syncthreads();
    }

    float* Cs = (float*)sm;
#pragma unroll
    for (int m = 0; m < 2; m++)
#pragma unroll
        for (int n = 0; n < 4; n++)
            wmma::store_matrix_sync(&Cs[(wm0 + m * 16) * LDCG + wn0 + n * 16],
                                    acc[m][n], LDCG, wmma::mem_row_major);
    __syncthreads();

#pragma unroll
    for (int rb = 0; rb < 8; rb++) {
        int r = rb * 16 + (tid >> 4);
        int c8 = (tid & 15) << 3;
#pragma unroll
        for (int q = 0; q < 2; q++) {
            int c = c8 + q * 4;
            float4 o = *(float4*)&Cs[r * LDCG + c];
            float4 bv = *(const float4*)(bias + colBase + c);
            o.x += bv.x; o.y += bv.y; o.z += bv.z; o.w += bv.w;
            if (RELU) {
                o.x = fmaxf(o.x, 0.f); o.y = fmaxf(o.y, 0.f);
                o.z = fmaxf(o.z, 0.f); o.w = fmaxf(o.w, 0.f);
            }
            if (RES) {
                float4 rv = *(const float4*)(res + (size_t)(rowBase + r) * 256 + colBase + c);
                o.x += rv.x; o.y += rv.y; o.z += rv.z; o.w += rv.w;
            }
            size_t gidx = (size_t)(rowBase + r) * 256 + colBase + c;
            *(float4*)(C + gidx) = o;
            if (SPLITOUT) {
                __nv_bfloat16 h0 = __float2bfloat16(o.x), h1 = __float2bfloat16(o.y);
                __nv_bfloat16 h2 = __float2bfloat16(o.z), h3 = __float2bfloat16(o.w);
                *(__nv_bfloat162*)(Ch + gidx)     = __nv_bfloat162(h0, h1);
                *(__nv_bfloat162*)(Ch + gidx + 2) = __nv_bfloat162(h2, h3);
                *(__nv_bfloat162*)(Cl + gidx) = __nv_bfloat162(
                    __float2bfloat16(o.x - __bfloat162float(h0)),
                    __float2bfloat16(o.y - __bfloat162float(h1)));
                *(__nv_bfloat162*)(Cl + gidx + 2) = __nv_bfloat162(
                    __float2bfloat16(o.z - __bfloat162float(h2)),
                    __float2bfloat16(o.w - __bfloat162float(h3)));
            }
        }
    }
}

__device__ __forceinline__ void split4s(__nv_bfloat16* H, __nv_bfloat16* L, int off, float4 v) {
    __nv_bfloat16 h0 = __float2bfloat16(v.x), h1 = __float2bfloat16(v.y);
    __nv_bfloat16 h2 = __float2bfloat16(v.z), h3 = __float2bfloat16(v.w);
    *(__nv_bfloat162*)(H + off)     = __nv_bfloat162(h0, h1);
    *(__nv_bfloat162*)(H + off + 2) = __nv_bfloat162(h2, h3);
    *(__nv_bfloat162*)(L + off) = __nv_bfloat162(
        __float2bfloat16(v.x - __bfloat162float(h0)),
        __float2bfloat16(v.y - __bfloat162float(h1)));
    *(__nv_bfloat162*)(L + off + 2) = __nv_bfloat162(
        __float2bfloat16(v.z - __bfloat162float(h2)),
        __float2bfloat16(v.w - __bfloat162float(h3)));
}

// ====== heads: dual GEMM (mu, lv). MODE 0: main pass. MODE 1: protected-row cleanup. ======
template<int MODE>
__global__ void __launch_bounds__(256, 2) heads_wmma(
    const float* __restrict__ enc2f,
    const __nv_bfloat16* __restrict__ e2h, const __nv_bfloat16* __restrict__ e2l,
    const float* __restrict__ W3f, const float* __restrict__ W4f,
    const __nv_bfloat16* __restrict__ W3h, const __nv_bfloat16* __restrict__ W3l,
    const __nv_bfloat16* __restrict__ W4h, const __nv_bfloat16* __restrict__ W4l,
    const float* __restrict__ b3, const float* __restrict__ b4,
    const float* __restrict__ eps,
    float* __restrict__ dstZ, __nv_bfloat16* __restrict__ zhi,
    float* __restrict__ klpart) {
    extern __shared__ __align__(16) char sm[];
    __nv_bfloat16* Ah  = (__nv_bfloat16*)sm;
    __nv_bfloat16* Al  = Ah + 128 * HLDA;
    __nv_bfloat16* P3h = Al + 128 * HLDA;
    __nv_bfloat16* P3l = P3h + 64 * LDW;
    __nv_bfloat16* P4h = P3l + 64 * LDW;
    __nv_bfloat16* P4l = P4h + 64 * LDW;
    int tid = threadIdx.x, wid = tid >> 5;
    int wm0 = (wid >> 1) * 32, wn0 = (wid & 1) * 32;
    int rowBase;
    if (MODE == 0) rowBase = blockIdx.y * 128;
    else           rowBase = (blockIdx.y < 2) ? 256 + blockIdx.y * 128
                                              : 3584 + (blockIdx.y - 2) * 128;
    int colBase = blockIdx.x * 64;

    wmma::fragment<wmma::accumulator, 16, 16, 16, float> ac3[2][2], ac4[2][2];
#pragma unroll
    for (int m = 0; m < 2; m++)
#pragma unroll
        for (int n = 0; n < 2; n++) {
            wmma::fill_fragment(ac3[m][n], 0.f);
            wmma::fill_fragment(ac4[m][n], 0.f);
        }

    for (int kc = 0; kc < 4; kc++) {
        int kg = kc * 64;
        if (MODE == 0) {
            for (int idx = tid; idx < 128 * 8; idx += 256) {
                int r = idx >> 3, c8 = (idx & 7) << 3;
                size_t g = (size_t)(rowBase + r) * 256 + kg + c8;
                *(uint4*)&Ah[r * HLDA + c8] = *(const uint4*)(e2h + g);
                *(uint4*)&Al[r * HLDA + c8] = *(const uint4*)(e2l + g);
            }
            for (int idx = tid; idx < 64 * 8; idx += 256) {
                int k = idx >> 3, c8 = (idx & 7) << 3;
                size_t g = (size_t)(kg + k) * 256 + colBase + c8;
                *(uint4*)&P3h[k * LDW + c8] = *(const uint4*)(W3h + g);
                *(uint4*)&P3l[k * LDW + c8] = *(const uint4*)(W3l + g);
                *(uint4*)&P4h[k * LDW + c8] = *(const uint4*)(W4h + g);
                *(uint4*)&P4l[k * LDW + c8] = *(const uint4*)(W4l + g);
            }
        } else {
            for (int idx = tid; idx < 128 * 16; idx += 256) {
                int r = idx >> 4, c4 = (idx & 15) << 2;
                float4 v = *(const float4*)(enc2f + (size_t)(rowBase + r) * 256 + kg + c4);
                split4s(Ah, Al, r * HLDA + c4, v);
            }
            for (int idx = tid; idx < 64 * 16; idx += 256) {
                int k = idx >> 4, c4 = (idx & 15) << 2;
                size_t g = (size_t)(kg + k) * 256 + colBase + c4;
                split4s(P3h, P3l, k * LDW + c4, *(const float4*)(W3f + g));
                split4s(P4h, P4l, k * LDW + c4, *(const float4*)(W4f + g));
            }
        }
        __syncthreads();
#pragma unroll
        for (int ks = 0; ks < 4; ks++) {
            int k0 = ks * 16;
            wmma::fragment<wmma::matrix_a, 16, 16, 16, __nv_bfloat16, wmma::row_major> aH[2], aL[2];
#pragma unroll
            for (int m = 0; m < 2; m++) {
                wmma::load_matrix_sync(aH[m], &Ah[(wm0 + m * 16) * HLDA + k0], HLDA);
                wmma::load_matrix_sync(aL[m], &Al[(wm0 + m * 16) * HLDA + k0], HLDA);
            }
            {
                wmma::fragment<wmma::matrix_b, 16, 16, 16, __nv_bfloat16, wmma::row_major> bH[2], bL[2];
#pragma unroll
                for (int n = 0; n < 2; n++) {
                    wmma::load_matrix_sync(bH[n], &P3h[k0 * LDW + wn0 + n * 16], LDW);
                    wmma::load_matrix_sync(bL[n], &P3l[k0 * LDW + wn0 + n * 16], LDW);
                }
#pragma unroll
                for (int m = 0; m < 2; m++)
#pragma unroll
                    for (int n = 0; n < 2; n++) {
                        wmma::mma_sync(ac3[m][n], aH[m], bH[n], ac3[m][n]);
                        wmma::mma_sync(ac3[m][n], aL[m], bH[n], ac3[m][n]);
                        wmma::mma_sync(ac3[m][n], aH[m], bL[n], ac3[m][n]);
                    }
            }
            {
                wmma::fragment<wmma::matrix_b, 16, 16, 16, __nv_bfloat16, wmma::row_major> bH[2], bL[2];
#pragma unroll
                for (int n = 0; n < 2; n++) {
                    wmma::load_matrix_sync(bH[n], &P4h[k0 * LDW + wn0 + n * 16], LDW);
                    wmma::load_matrix_sync(bL[n], &P4l[k0 * LDW + wn0 + n * 16], LDW);
                }
#pragma unroll
                for (int m = 0; m < 2; m++)
#pragma unroll
                    for (int n = 0; n < 2; n++) {
                        wmma::mma_sync(ac4[m][n], aH[m], bH[n], ac4[m][n]);
                        wmma::mma_sync(ac4[m][n], aL[m], bH[n], ac4[m][n]);
                        wmma::mma_sync(ac4[m][n], aH[m], bL[n], ac4[m][n]);
                    }
            }
        }
        __syncthreads();
    }

    float* Cmu = (float*)sm;
    float* Clv = Cmu + 128 * LDC;
#pragma unroll
    for (int m = 0; m < 2; m++)
#pragma unroll
        for (int n = 0; n < 2; n++) {
            wmma::store_matrix_sync(&Cmu[(wm0 + m * 16) * LDC + wn0 + n * 16],
                                    ac3[m][n], LDC, wmma::mem_row_major);
            wmma::store_matrix_sync(&Clv[(wm0 + m * 16) * LDC + wn0 + n * 16],
                                    ac4[m][n], LDC, wmma::mem_row_major);
        }
    __syncthreads();

    bool zwrite = (MODE == 1) || !row_protected(rowBase);
    float klsum = 0.f;
#pragma unroll
    for (int rb = 0; rb < 8; rb++) {
        int r = rb * 16 + (tid >> 4);
        int c = (tid & 15) << 2;
        int n = rowBase + r;
        int col = colBase + c;
        float4 mu4 = *(float4*)&Cmu[r * LDC + c];
        float4 lv4 = *(float4*)&Clv[r * LDC + c];
        float4 b3v = *(const float4*)(b3 + col);
        float4 b4v = *(const float4*)(b4 + col);
        float mu[4] = {mu4.x + b3v.x, mu4.y + b3v.y, mu4.z + b3v.z, mu4.w + b3v.w};
        float lv[4] = {lv4.x + b4v.x, lv4.y + b4v.y, lv4.z + b4v.z, lv4.w + b4v.w};
        float sg[4];
#pragma unroll
        for (int j = 0; j < 4; j++) sg[j] = __expf(0.5f * lv[j]);

        float4 es = make_float4(0.f, 0.f, 0.f, 0.f);
#pragma unroll
        for (int k = 0; k < KK; k++) {
            float4 e = *(const float4*)(eps + (size_t)(n * KK + k) * DD + col);
            if (MODE == 0) { es.x += e.x; es.y += e.y; es.z += e.z; es.w += e.w; }
            if (zwrite) {
                float4 o;
                o.x = fmaf(sg[0], e.x, mu[0]);
                o.y = fmaf(sg[1], e.y, mu[1]);
                o.z = fmaf(sg[2], e.z, mu[2]);
                o.w = fmaf(sg[3], e.w, mu[3]);
                *(float4*)(dstZ + (size_t)(n * KK + k) * DD + col) = o;
            }
        }
        if (MODE == 0) {
            float zv[4];
            zv[0] = fmaf(sg[0], es.x * 0.125f, mu[0]);
            zv[1] = fmaf(sg[1], es.y * 0.125f, mu[1]);
            zv[2] = fmaf(sg[2], es.z * 0.125f, mu[2]);
            zv[3] = fmaf(sg[3], es.w * 0.125f, mu[3]);
            size_t base = (size_t)n * DD + col;
            *(__nv_bfloat162*)(zhi + base) =
                __nv_bfloat162(__float2bfloat16(zv[0]), __float2bfloat16(zv[1]));
            *(__nv_bfloat162*)(zhi + base + 2) =
                __nv_bfloat162(__float2bfloat16(zv[2]), __float2bfloat16(zv[3]));
#pragma unroll
            for (int j = 0; j < 4; j++)
                klsum += 1.f + lv[j] - mu[j] * mu[j] - sg[j] * sg[j];
        }
    }

    if (MODE == 0) {
        __shared__ float sred[256];
        sred[tid] = klsum; __syncthreads();
        for (int s = 128; s > 0; s >>= 1) {
            if (tid < s) sred[tid] += sred[tid + s];
            __syncthreads();
        }
        if (tid == 0) klpart[blockIdx.y * 4 + blockIdx.x] = sred[0];
    }
}

// ====== WMMA bf16 loss: triangular 1-D grid, 128x128 tiles ======
__global__ void __launch_bounds__(256, 2) loss_mma_kernel(
    const __nv_bfloat16* __restrict__ zhi,
    const float* __restrict__ ADJ, float* __restrict__ glpart) {
    int tid = threadIdx.x;
    // map linear block id -> (bi, bj) with bi <= bj over 64x64
    int idx = blockIdx.x;
    int bi = (int)((129.0 - sqrt(129.0 * 129.0 - 8.0 * idx)) * 0.5);
    // start(bi) = bi*64 - bi*(bi-1)/2 ; correct for fp rounding
    while (bi * 64 - bi * (bi - 1) / 2 > idx) bi--;
    while ((bi + 1) * 64 - (bi + 1) * bi / 2 <= idx) bi++;
    int bj = bi + (idx - (bi * 64 - bi * (bi - 1) / 2));
    int rowBase = bi * 128, colBase = bj * 128;

    extern __shared__ __align__(16) char smc[];
    __nv_bfloat16* AH = (__nv_bfloat16*)smc;
    __nv_bfloat16* BH = AH + 128 * LDA;

    int wid = tid >> 5;
    int wm0 = (wid >> 1) * 32;
    int wn0 = (wid & 1) * 64;

    wmma::fragment<wmma::accumulator, 16, 16, 16, float> acc[2][4];
#pragma unroll
    for (int m = 0; m < 2; m++)
#pragma unroll
        for (int n = 0; n < 4; n++) wmma::fill_fragment(acc[m][n], 0.f);

    for (int kc = 0; kc < 2; kc++) {
        int kg = kc * 128;
        for (int i2 = tid; i2 < 128 * 16; i2 += 256) {
            int r = i2 >> 4, c8 = (i2 & 15) << 3;
            *(uint4*)&AH[r * LDA + c8] =
                *(const uint4*)(zhi + (size_t)(rowBase + r) * 256 + kg + c8);
            *(uint4*)&BH[r * LDA + c8] =
                *(const uint4*)(zhi + (size_t)(colBase + r) * 256 + kg + c8);
        }
        __syncthreads();
#pragma unroll
        for (int ks = 0; ks < 8; ks++) {
            int k0 = ks * 16;
            wmma::fragment<wmma::matrix_a, 16, 16, 16, __nv_bfloat16, wmma::row_major> aH[2];
#pragma unroll
            for (int m = 0; m < 2; m++)
                wmma::load_matrix_sync(aH[m], &AH[(wm0 + m * 16) * LDA + k0], LDA);
#pragma unroll
            for (int n = 0; n < 4; n++) {
                wmma::fragment<wmma::matrix_b, 16, 16, 16, __nv_bfloat16, wmma::col_major> bH;
                wmma::load_matrix_sync(bH, &BH[(wn0 + n * 16) * LDA + k0], LDA);
#pragma unroll
                for (int m = 0; m < 2; m++)
                    wmma::mma_sync(acc[m][n], aH[m], bH, acc[m][n]);
            }
        }
        __syncthreads();
    }

    float* Cs = (float*)smc;
#pragma unroll
    for (int m = 0; m < 2; m++)
#pragma unroll
        for (int n = 0; n < 4; n++)
            wmma::store_matrix_sync(&Cs[(wm0 + m * 16) * LDC2 + wn0 + n * 16],
                                    acc[m][n], LDC2, wmma::mem_row_major);
    __syncthreads();

    float term = 0.f;
    bool offdiag = (bi != bj);
    {
        int jl4 = (tid & 31) << 2;
        int j0 = colBase + jl4;
        for (int il = tid >> 5; il < 128; il += 8) {
            int i = rowBase + il;
            float4 c4 = *(float4*)&Cs[il * LDC2 + jl4];
            float4 a4 = *(const float4*)(ADJ + (size_t)i * NN + j0);
            float cs[4] = {c4.x, c4.y, c4.z, c4.w};
            float as[4] = {a4.x, a4.y, a4.z, a4.w};
            if (offdiag || i < j0) {
#pragma unroll
                for (int t = 0; t < 4; t++) {
                    float c = cs[t];
                    float sp = fmaxf(c, 0.f) + __logf(1.f + __expf(-fabsf(c)));
                    term += 2.f * sp - c * as[t];
                }
            } else {
#pragma unroll
                for (int t = 0; t < 4; t++) {
                    int j = j0 + t;
                    if (i > j) continue;
                    float c = cs[t];
                    float sp = fmaxf(c, 0.f) + __logf(1.f + __expf(-fabsf(c)));
                    term += (i < j ? 2.f : 1.f) * sp - c * as[t];
                }
            }
        }
    }
    {
        int il4 = (tid & 31) << 2;
        int i0 = rowBase + il4;
        for (int jl = tid >> 5; jl < 128; jl += 8) {
            int j = colBase + jl;
            float4 a4 = *(const float4*)(ADJ + (size_t)j * NN + i0);
            float as[4] = {a4.x, a4.y, a4.z, a4.w};
            if (offdiag || i0 + 3 < j) {
#pragma unroll
                for (int t = 0; t < 4; t++)
                    term -= Cs[(il4 + t) * LDC2 + jl] * as[t];
            } else {
#pragma unroll
                for (int t = 0; t < 4; t++)
                    if (i0 + t < j)
                        term -= Cs[(il4 + t) * LDC2 + jl] * as[t];
            }
        }
    }

    __shared__ float sred[256];
    sred[tid] = term; __syncthreads();
    for (int s = 128; s > 0; s >>= 1) {
        if (tid < s) sred[tid] += sred[tid + s];
        __syncthreads();
    }
    if (tid == 0) glpart[blockIdx.x] = sred[0];
}

// ================= final reduction =================
__global__ void finalize_kernel(const float* __restrict__ klpart,
                                const float* __restrict__ glpart,
                                float* __restrict__ outScalar) {
    __shared__ double sk[256], sg[256];
    int t = threadIdx.x;
    double a = (double)klpart[t];
    double b = 0.0;
    for (int i = t; i < NLOSS; i += 256) b += (double)glpart[i];
    sk[t] = a; sg[t] = b; __syncthreads();
    for (int s = 128; s > 0; s >>= 1) {
        if (t < s) { sk[t] += sk[t + s]; sg[t] += sg[t + s]; }
        __syncthreads();
    }
    if (t == 0) {
        double kl = -0.5 * sk[0] / (double)NN;
        double gl = sg[0] / ((double)NN * (double)NN);
        *outScalar = (float)(kl + gl);
    }
}

// ================= host launcher =================
extern "C" void kernel_launch(void* const* d_in, const int* in_sizes, int n_in,
                              void* d_out, int out_size) {
    const float* enc = (const float*)d_in[0];
    const int*   ei  = (const int*)d_in[1];
    const float* w   = (const float*)d_in[2];
    const float* ADJ = (const float*)d_in[3];
    const float* eps = (const float*)d_in[4];
    const float* W1 = (const float*)d_in[5];  const float* b1 = (const float*)d_in[6];
    const float* W2 = (const float*)d_in[7];  const float* b2 = (const float*)d_in[8];
    const float* W3 = (const float*)d_in[9];  const float* b3 = (const float*)d_in[10];
    const float* W4 = (const float*)d_in[11]; const float* b4 = (const float*)d_in[12];

    float* out  = (float*)d_out;
    float* enc2 = out;
    float* zreg = out + (size_t)NN * DD;

    int*   deg  = (int*)  (zreg + S_DEG);
    int*   off  = (int*)  (zreg + S_OFF);
    int*   cur  = (int*)  (zreg + S_CUR);
    int*   esrc = (int*)  (zreg + S_ESRC);
    float* ew   =          zreg + S_EW;
    __nv_bfloat16* wsp = (__nv_bfloat16*)(zreg + S_WSP);
    __nv_bfloat16* hch = (__nv_bfloat16*)(zreg + S_HCH);
    __nv_bfloat16* hcl = (__nv_bfloat16*)(zreg + S_HCL);
    float* h1   =          zreg + S_H1;
    __nv_bfloat16* e2h = (__nv_bfloat16*)(zreg + S_E2H);
    __nv_bfloat16* e2l = (__nv_bfloat16*)(zreg + S_E2L);
    __nv_bfloat16* zhi = (__nv_bfloat16*)(zreg + S_ZLH);
    float* klp  =          zreg + S_KLP;
    float* glp  =          zreg + S_GLP;
    float* outScalar = out + (size_t)out_size - 1;

    cudaFuncSetAttribute(loss_mma_kernel,
                         cudaFuncAttributeMaxDynamicSharedMemorySize, LOSS_SMEM);
    cudaFuncSetAttribute(gemm_bf16<true, false, false, 512>,
                         cudaFuncAttributeMaxDynamicSharedMemorySize, GW_SMEM);
    cudaFuncSetAttribute(gemm_bf16<true, true, true, 512>,
                         cudaFuncAttributeMaxDynamicSharedMemorySize, GW_SMEM);
    cudaFuncSetAttribute(heads_wmma<0>,
                         cudaFuncAttributeMaxDynamicSharedMemorySize, HD_SMEM);
    cudaFuncSetAttribute(heads_wmma<1>,
                         cudaFuncAttributeMaxDynamicSharedMemorySize, HD_SMEM);

    // weight pre-split + deg zero (fused), then CSR build (4 edges/thread)
    split_w_all<<<384, 256>>>(W1, W2, W3, W4, wsp, deg);
    hist_kernel<<<EE / 1024, 256>>>(ei, deg);
    scan_kernel<<<1, 256>>>(deg, off, cur);
    fill_kernel<<<EE / 1024, 256>>>(ei, w, cur, esrc, ew);

    // conv1 + linear1 + relu
    gather_kernel<<<NN, 256>>>(enc, hch, hcl, deg, off, esrc, ew);
    gemm_bf16<true, false, false, 512><<<dim3(2, 64), 256, GW_SMEM>>>(
        hch, hcl, wsp + W1H, wsp + W1L, b1, nullptr, h1, nullptr, nullptr);

    // conv2 + linear2 + relu + residual -> enc2 (+ split copies)
    gather_kernel<<<NN, 256>>>(h1, hch, hcl, deg, off, esrc, ew);
    gemm_bf16<true, true, true, 512><<<dim3(2, 64), 256, GW_SMEM>>>(
        hch, hcl, wsp + W2H, wsp + W2L, b2, enc, enc2, e2h, e2l);

    // heads: dual GEMM -> Zl + KL partials + Z for non-protected rows
    heads_wmma<0><<<dim3(4, 64), 256, HD_SMEM>>>(
        nullptr, e2h, e2l, nullptr, nullptr,
        wsp + W3H, wsp + W3L, wsp + W4H, wsp + W4L,
        b3, b4, eps, zreg, zhi, klp);

    // loss GEMM + BCE (triangular 1-D grid)
    loss_mma_kernel<<<NLOSS, 256, LOSS_SMEM>>>(zhi, ADJ, glp);

    // loss scalar (reads klp/glp before cleanup overwrites them)
    finalize_kernel<<<1, 256>>>(klp, glp, outScalar);

    // cleanup: write Z for the 15 protected row-blocks (self-splitting)
    heads_wmma<1><<<dim3(4, 15), 256, HD_SMEM>>>(
        enc2, nullptr, nullptr, W3, W4,
        nullptr, nullptr, nullptr, nullptr,
        b3, b4, eps, zreg, nullptr, nullptr);
}

// round 15
// speedup vs baseline: 1.0138x; 1.0138x over previous
#include <cuda_runtime.h>
#include <cuda_bf16.h>
#include <mma.h>
#include <math.h>
#include <stdint.h>

using namespace nvcuda;

#define NN 8192
#define DD 256
#define EE 262144
#define KK 8

// ---- arena layout inside Z region of d_out (16,777,216 floats) ----
// Z row n occupies floats [n*2048, (n+1)*2048)
#define S_DEG   0
#define S_OFF   8192
#define S_CUR   16384
#define S_ESRC  24576
#define S_EW    286720
#define S_WSP   548864                 // 393,216 floats of bf16 weight splits -> rows [268,460)
#define S_ZLH   942080                 // zhi: 1,048,576 floats -> rows [460,972)
#define S_KLP   1990656                // 256 floats
#define S_GLP   1990912                // 2080 floats -> ends row ~973
#define S_HCH   2097152                // hcat_hi (2,097,152 floats) rows [1024,2048)
#define S_HCL   4194304                // hcat_lo rows [2048,3072)
#define S_H1    6291456                // h1 fp32 rows [3072,4096)

// protected Z row-blocks during heads<0>/loss/finalize: [256,1024)
__device__ __forceinline__ bool row_protected(int rowBase) {
    return (rowBase >= 256 && rowBase < 1024);
}

#define W1H 0
#define W1L 131072
#define W2H 262144
#define W2L 393216
#define W3H 524288
#define W3L 589824
#define W4H 655360
#define W4L 720896

#define HLDA 72
#define LDW 72
#define LDW2 136
#define LDC 72
#define LDCG 136
#define GW_SMEM  71680
#define HD_SMEM  73728
#define LDC2 132
#define LOSS_SMEM 69632
#define LDA 136
#define NLOSS 2080          // 64*65/2 triangular blocks

// ================= CSR build (scalar, 1 edge/thread — max warps) =================
__global__ void hist_kernel(const int* __restrict__ ei, int* deg) {
    int e = blockIdx.x * 256 + threadIdx.x;
    atomicAdd(&deg[ei[EE + e]], 1);
}
__global__ void scan_kernel(const int* __restrict__ deg, int* off, int* cur) {
    __shared__ int s[256];
    int tid = threadIdx.x;
    int base = tid * 32;
    int loc[32];
    int sum = 0;
#pragma unroll
    for (int i = 0; i < 32; i++) { loc[i] = deg[base + i]; sum += loc[i]; }
    s[tid] = sum;
    __syncthreads();
    for (int o = 1; o < 256; o <<= 1) {
        int v = (tid >= o) ? s[tid - o] : 0;
        __syncthreads();
        s[tid] += v;
        __syncthreads();
    }
    int run = s[tid] - sum;
#pragma unroll
    for (int i = 0; i < 32; i++) {
        off[base + i] = run;
        cur[base + i] = run;
        run += loc[i];
    }
}
__global__ void fill_kernel(const int* __restrict__ ei, const float* __restrict__ w,
                            int* cur, int* esrc, float* ew) {
    int e = blockIdx.x * 256 + threadIdx.x;
    int src = ei[e];
    int dst = ei[EE + e];
    int slot = atomicAdd(&cur[dst], 1);
    esrc[slot] = src;
    ew[slot]   = w[e];
}

// ============ fused: zero deg + split all 4 weights ============
__global__ void split_w_all(const float* __restrict__ W1, const float* __restrict__ W2,
                            const float* __restrict__ W3, const float* __restrict__ W4,
                            __nv_bfloat16* __restrict__ wsp, int* __restrict__ deg) {
    int gid = blockIdx.x * 256 + threadIdx.x;
    if (gid < NN) deg[gid] = 0;
    int idx4 = gid * 4;
    const float* src;
    int local;
    __nv_bfloat16 *dh, *dl;
    if (idx4 < 131072)      { src = W1; local = idx4;          dh = wsp + W1H; dl = wsp + W1L; }
    else if (idx4 < 262144) { src = W2; local = idx4 - 131072; dh = wsp + W2H; dl = wsp + W2L; }
    else if (idx4 < 327680) { src = W3; local = idx4 - 262144; dh = wsp + W3H; dl = wsp + W3L; }
    else                    { src = W4; local = idx4 - 327680; dh = wsp + W4H; dl = wsp + W4L; }
    float4 v = *(const float4*)(src + local);
    __nv_bfloat16 h0 = __float2bfloat16(v.x), h1 = __float2bfloat16(v.y);
    __nv_bfloat16 h2 = __float2bfloat16(v.z), h3 = __float2bfloat16(v.w);
    *(__nv_bfloat162*)(dh + local)     = __nv_bfloat162(h0, h1);
    *(__nv_bfloat162*)(dh + local + 2) = __nv_bfloat162(h2, h3);
    *(__nv_bfloat162*)(dl + local) = __nv_bfloat162(
        __float2bfloat16(v.x - __bfloat162float(h0)),
        __float2bfloat16(v.y - __bfloat162float(h1)));
    *(__nv_bfloat162*)(dl + local + 2) = __nv_bfloat162(
        __float2bfloat16(v.z - __bfloat162float(h2)),
        __float2bfloat16(v.w - __bfloat162float(h3)));
}

// ============ gather conv + combine (4 independent accumulators) ============
__global__ void gather_kernel(const float* __restrict__ x,
                              __nv_bfloat16* __restrict__ hch,
                              __nv_bfloat16* __restrict__ hcl,
                              const int* __restrict__ deg, const int* __restrict__ off,
                              const int* __restrict__ esrc, const float* __restrict__ ew) {
    __shared__ int   ss[256];
    __shared__ float sw[256];
    int n = blockIdx.x, d = threadIdx.x;
    int beg = off[n];
    int dg  = deg[n];
    float a0 = 0.f, a1 = 0.f, a2 = 0.f, a3 = 0.f;
    for (int c = 0; c < dg; c += 256) {
        int m = min(256, dg - c);
        if (d < m) { ss[d] = esrc[beg + c + d]; sw[d] = ew[beg + c + d]; }
        __syncthreads();
        int j = 0;
        for (; j + 3 < m; j += 4) {
            a0 = fmaf(x[(size_t)ss[j + 0] * DD + d], sw[j + 0], a0);
            a1 = fmaf(x[(size_t)ss[j + 1] * DD + d], sw[j + 1], a1);
            a2 = fmaf(x[(size_t)ss[j + 2] * DD + d], sw[j + 2], a2);
            a3 = fmaf(x[(size_t)ss[j + 3] * DD + d], sw[j + 3], a3);
        }
        for (; j < m; j++)
            a0 = fmaf(x[(size_t)ss[j] * DD + d], sw[j], a0);
        __syncthreads();
    }
    float acc = (a0 + a1) + (a2 + a3);
    float xv = x[(size_t)n * DD + d];
    float av = acc / fmaxf((float)dg, 1.f);
    __nv_bfloat16 xh = __float2bfloat16(xv);
    __nv_bfloat16 ah = __float2bfloat16(av);
    int base = n * 512 + d;
    hch[base]       = xh;
    hch[base + 256] = ah;
    hcl[base]       = __float2bfloat16(xv - __bfloat162float(xh));
    hcl[base + 256] = __float2bfloat16(av - __bfloat162float(ah));
}

// ====== bf16 GEMM, N-tile 128, K-chunk 64: C = act(A@W + b) (+res) ======
template<bool RELU, bool RES, int KD>
__global__ void __launch_bounds__(256, 2) gemm_bf16(
    const __nv_bfloat16* __restrict__ Ahg, const __nv_bfloat16* __restrict__ Alg,
    const __nv_bfloat16* __restrict__ Whg, const __nv_bfloat16* __restrict__ Wlg,
    const float* __restrict__ bias, const float* __restrict__ res,
    float* __restrict__ C) {
    extern __shared__ __align__(16) char sm[];
    __nv_bfloat16* Ah = (__nv_bfloat16*)sm;
    __nv_bfloat16* Al = Ah + 128 * HLDA;
    __nv_bfloat16* Wh = Al + 128 * HLDA;
    __nv_bfloat16* Wl = Wh + 64 * LDW2;
    int tid = threadIdx.x, wid = tid >> 5;
    int wm0 = (wid & 3) * 32, wn0 = (wid >> 2) * 64;
    int rowBase = blockIdx.y * 128, colBase = blockIdx.x * 128;

    wmma::fragment<wmma::accumulator, 16, 16, 16, float> acc[2][4];
#pragma unroll
    for (int m = 0; m < 2; m++)
#pragma unroll
        for (int n = 0; n < 4; n++) wmma::fill_fragment(acc[m][n], 0.f);

    for (int kc = 0; kc < KD / 64; kc++) {
        int kg = kc * 64;
        for (int idx = tid; idx < 128 * 8; idx += 256) {
            int r = idx >> 3, c8 = (idx & 7) << 3;
            size_t g = (size_t)(rowBase + r) * KD + kg + c8;
            *(uint4*)&Ah[r * HLDA + c8] = *(const uint4*)(Ahg + g);
            *(uint4*)&Al[r * HLDA + c8] = *(const uint4*)(Alg + g);
        }
        for (int idx = tid; idx < 64 * 16; idx += 256) {
            int k = idx >> 4, c8 = (idx & 15) << 3;
            size_t g = (size_t)(kg + k) * 256 + colBase + c8;
            *(uint4*)&Wh[k * LDW2 + c8] = *(const uint4*)(Whg + g);
            *(uint4*)&Wl[k * LDW2 + c8] = *(const uint4*)(Wlg + g);
        }
        __syncthreads();
#pragma unroll
        for (int ks = 0; ks < 4; ks++) {
            int k0 = ks * 16;
            wmma::fragment<wmma::matrix_a, 16, 16, 16, __nv_bfloat16, wmma::row_major> aH[2], aL[2];
#pragma unroll
            for (int m = 0; m < 2; m++) {
                wmma::load_matrix_sync(aH[m], &Ah[(wm0 + m * 16) * HLDA + k0], HLDA);
                wmma::load_matrix_sync(aL[m], &Al[(wm0 + m * 16) * HLDA + k0], HLDA);
            }
#pragma unroll
            for (int n = 0; n < 4; n++) {
                wmma::fragment<wmma::matrix_b, 16, 16, 16, __nv_bfloat16, wmma::row_major> bH, bL;
                wmma::load_matrix_sync(bH, &Wh[k0 * LDW2 + wn0 + n * 16], LDW2);
                wmma::load_matrix_sync(bL, &Wl[k0 * LDW2 + wn0 + n * 16], LDW2);
#pragma unroll
                for (int m = 0; m < 2; m++) {
                    wmma::mma_sync(acc[m][n], aH[m], bH, acc[m][n]);
                    wmma::mma_sync(acc[m][n], aL[m], bH, acc[m][n]);
                    wmma::mma_sync(acc[m][n], aH[m], bL, acc[m][n]);
                }
            }
        }
        __syncthreads();
    }

    float* Cs = (float*)sm;
#pragma unroll
    for (int m = 0; m < 2; m++)
#pragma unroll
        for (int n = 0; n < 4; n++)
            wmma::store_matrix_sync(&Cs[(wm0 + m * 16) * LDCG + wn0 + n * 16],
                                    acc[m][n], LDCG, wmma::mem_row_major);
    __syncthreads();

#pragma unroll
    for (int rb = 0; rb < 8; rb++) {
        int r = rb * 16 + (tid >> 4);
        int c8 = (tid & 15) << 3;
#pragma unroll
        for (int q = 0; q < 2; q++) {
            int c = c8 + q * 4;
            float4 o = *(float4*)&Cs[r * LDCG + c];
            float4 bv = *(const float4*)(bias + colBase + c);
            o.x += bv.x; o.y += bv.y; o.z += bv.z; o.w += bv.w;
            if (RELU) {
                o.x = fmaxf(o.x, 0.f); o.y = fmaxf(o.y, 0.f);
                o.z = fmaxf(o.z, 0.f); o.w = fmaxf(o.w, 0.f);
            }
            if (RES) {
                float4 rv = *(const float4*)(res + (size_t)(rowBase + r) * 256 + colBase + c);
                o.x += rv.x; o.y += rv.y; o.z += rv.z; o.w += rv.w;
            }
            *(float4*)(C + (size_t)(rowBase + r) * 256 + colBase + c) = o;
        }
    }
}

__device__ __forceinline__ void split4s(__nv_bfloat16* H, __nv_bfloat16* L, int off, float4 v) {
    __nv_bfloat16 h0 = __float2bfloat16(v.x), h1 = __float2bfloat16(v.y);
    __nv_bfloat16 h2 = __float2bfloat16(v.z), h3 = __float2bfloat16(v.w);
    *(__nv_bfloat162*)(H + off)     = __nv_bfloat162(h0, h1);
    *(__nv_bfloat162*)(H + off + 2) = __nv_bfloat162(h2, h3);
    *(__nv_bfloat162*)(L + off) = __nv_bfloat162(
        __float2bfloat16(v.x - __bfloat162float(h0)),
        __float2bfloat16(v.y - __bfloat162float(h1)));
    *(__nv_bfloat162*)(L + off + 2) = __nv_bfloat162(
        __float2bfloat16(v.z - __bfloat162float(h2)),
        __float2bfloat16(v.w - __bfloat162float(h3)));
}

// ====== heads: dual GEMM (mu, lv). A self-split from fp32 enc2 in both modes.
// MODE 0: W pre-split; writes Zl + KL partials + Z for non-protected rows.
// MODE 1: cleanup; W self-split from fp32; writes Z only for protected rows.
template<int MODE>
__global__ void __launch_bounds__(256, 2) heads_wmma(
    const float* __restrict__ enc2f,
    const float* __restrict__ W3f, const float* __restrict__ W4f,
    const __nv_bfloat16* __restrict__ W3h, const __nv_bfloat16* __restrict__ W3l,
    const __nv_bfloat16* __restrict__ W4h, const __nv_bfloat16* __restrict__ W4l,
    const float* __restrict__ b3, const float* __restrict__ b4,
    const float* __restrict__ eps,
    float* __restrict__ dstZ, __nv_bfloat16* __restrict__ zhi,
    float* __restrict__ klpart) {
    extern __shared__ __align__(16) char sm[];
    __nv_bfloat16* Ah  = (__nv_bfloat16*)sm;
    __nv_bfloat16* Al  = Ah + 128 * HLDA;
    __nv_bfloat16* P3h = Al + 128 * HLDA;
    __nv_bfloat16* P3l = P3h + 64 * LDW;
    __nv_bfloat16* P4h = P3l + 64 * LDW;
    __nv_bfloat16* P4l = P4h + 64 * LDW;
    int tid = threadIdx.x, wid = tid >> 5;
    int wm0 = (wid >> 1) * 32, wn0 = (wid & 1) * 32;
    int rowBase = (MODE == 0) ? blockIdx.y * 128 : 256 + blockIdx.y * 128;
    int colBase = blockIdx.x * 64;

    wmma::fragment<wmma::accumulator, 16, 16, 16, float> ac3[2][2], ac4[2][2];
#pragma unroll
    for (int m = 0; m < 2; m++)
#pragma unroll
        for (int n = 0; n < 2; n++) {
            wmma::fill_fragment(ac3[m][n], 0.f);
            wmma::fill_fragment(ac4[m][n], 0.f);
        }

    for (int kc = 0; kc < 4; kc++) {
        int kg = kc * 64;
        // A: self-split from fp32 enc2 (both modes)
        for (int idx = tid; idx < 128 * 16; idx += 256) {
            int r = idx >> 4, c4 = (idx & 15) << 2;
            float4 v = *(const float4*)(enc2f + (size_t)(rowBase + r) * 256 + kg + c4);
            split4s(Ah, Al, r * HLDA + c4, v);
        }
        if (MODE == 0) {
            for (int idx = tid; idx < 64 * 8; idx += 256) {
                int k = idx >> 3, c8 = (idx & 7) << 3;
                size_t g = (size_t)(kg + k) * 256 + colBase + c8;
                *(uint4*)&P3h[k * LDW + c8] = *(const uint4*)(W3h + g);
                *(uint4*)&P3l[k * LDW + c8] = *(const uint4*)(W3l + g);
                *(uint4*)&P4h[k * LDW + c8] = *(const uint4*)(W4h + g);
                *(uint4*)&P4l[k * LDW + c8] = *(const uint4*)(W4l + g);
            }
        } else {
            for (int idx = tid; idx < 64 * 16; idx += 256) {
                int k = idx >> 4, c4 = (idx & 15) << 2;
                size_t g = (size_t)(kg + k) * 256 + colBase + c4;
                split4s(P3h, P3l, k * LDW + c4, *(const float4*)(W3f + g));
                split4s(P4h, P4l, k * LDW + c4, *(const float4*)(W4f + g));
            }
        }
        __syncthreads();
#pragma unroll
        for (int ks = 0; ks < 4; ks++) {
            int k0 = ks * 16;
            wmma::fragment<wmma::matrix_a, 16, 16, 16, __nv_bfloat16, wmma::row_major> aH[2], aL[2];
#pragma unroll
            for (int m = 0; m < 2; m++) {
                wmma::load_matrix_sync(aH[m], &Ah[(wm0 + m * 16) * HLDA + k0], HLDA);
                wmma::load_matrix_sync(aL[m], &Al[(wm0 + m * 16) * HLDA + k0], HLDA);
            }
            {
                wmma::fragment<wmma::matrix_b, 16, 16, 16, __nv_bfloat16, wmma::row_major> bH[2], bL[2];
#pragma unroll
                for (int n = 0; n < 2; n++) {
                    wmma::load_matrix_sync(bH[n], &P3h[k0 * LDW + wn0 + n * 16], LDW);
                    wmma::load_matrix_sync(bL[n], &P3l[k0 * LDW + wn0 + n * 16], LDW);
                }
#pragma unroll
                for (int m = 0; m < 2; m++)
#pragma unroll
                    for (int n = 0; n < 2; n++) {
                        wmma::mma_sync(ac3[m][n], aH[m], bH[n], ac3[m][n]);
                        wmma::mma_sync(ac3[m][n], aL[m], bH[n], ac3[m][n]);
                        wmma::mma_sync(ac3[m][n], aH[m], bL[n], ac3[m][n]);
                    }
            }
            {
                wmma::fragment<wmma::matrix_b, 16, 16, 16, __nv_bfloat16, wmma::row_major> bH[2], bL[2];
#pragma unroll
                for (int n = 0; n < 2; n++) {
                    wmma::load_matrix_sync(bH[n], &P4h[k0 * LDW + wn0 + n * 16], LDW);
                    wmma::load_matrix_sync(bL[n], &P4l[k0 * LDW + wn0 + n * 16], LDW);
                }
#pragma unroll
                for (int m = 0; m < 2; m++)
#pragma unroll
                    for (int n = 0; n < 2; n++) {
                        wmma::mma_sync(ac4[m][n], aH[m], bH[n], ac4[m][n]);
                        wmma::mma_sync(ac4[m][n], aL[m], bH[n], ac4[m][n]);
                        wmma::mma_sync(ac4[m][n], aH[m], bL[n], ac4[m][n]);
                    }
            }
        }
        __syncthreads();
    }

    float* Cmu = (float*)sm;
    float* Clv = Cmu + 128 * LDC;
#pragma unroll
    for (int m = 0; m < 2; m++)
#pragma unroll
        for (int n = 0; n < 2; n++) {
            wmma::store_matrix_sync(&Cmu[(wm0 + m * 16) * LDC + wn0 + n * 16],
                                    ac3[m][n], LDC, wmma::mem_row_major);
            wmma::store_matrix_sync(&Clv[(wm0 + m * 16) * LDC + wn0 + n * 16],
                                    ac4[m][n], LDC, wmma::mem_row_major);
        }
    __syncthreads();

    bool zwrite = (MODE == 1) || !row_protected(rowBase);
    float klsum = 0.f;
#pragma unroll
    for (int rb = 0; rb < 8; rb++) {
        int r = rb * 16 + (tid >> 4);
        int c = (tid & 15) << 2;
        int n = rowBase + r;
        int col = colBase + c;
        float4 mu4 = *(float4*)&Cmu[r * LDC + c];
        float4 lv4 = *(float4*)&Clv[r * LDC + c];
        float4 b3v = *(const float4*)(b3 + col);
        float4 b4v = *(const float4*)(b4 + col);
        float mu[4] = {mu4.x + b3v.x, mu4.y + b3v.y, mu4.z + b3v.z, mu4.w + b3v.w};
        float lv[4] = {lv4.x + b4v.x, lv4.y + b4v.y, lv4.z + b4v.z, lv4.w + b4v.w};
        float sg[4];
#pragma unroll
        for (int j = 0; j < 4; j++) sg[j] = __expf(0.5f * lv[j]);

        float4 es = make_float4(0.f, 0.f, 0.f, 0.f);
#pragma unroll
        for (int k = 0; k < KK; k++) {
            float4 e = *(const float4*)(eps + (size_t)(n * KK + k) * DD + col);
            if (MODE == 0) { es.x += e.x; es.y += e.y; es.z += e.z; es.w += e.w; }
            if (zwrite) {
                float4 o;
                o.x = fmaf(sg[0], e.x, mu[0]);
                o.y = fmaf(sg[1], e.y, mu[1]);
                o.z = fmaf(sg[2], e.z, mu[2]);
                o.w = fmaf(sg[3], e.w, mu[3]);
                *(float4*)(dstZ + (size_t)(n * KK + k) * DD + col) = o;
            }
        }
        if (MODE == 0) {
            float zv[4];
            zv[0] = fmaf(sg[0], es.x * 0.125f, mu[0]);
            zv[1] = fmaf(sg[1], es.y * 0.125f, mu[1]);
            zv[2] = fmaf(sg[2], es.z * 0.125f, mu[2]);
            zv[3] = fmaf(sg[3], es.w * 0.125f, mu[3]);
            size_t base = (size_t)n * DD + col;
            *(__nv_bfloat162*)(zhi + base) =
                __nv_bfloat162(__float2bfloat16(zv[0]), __float2bfloat16(zv[1]));
            *(__nv_bfloat162*)(zhi + base + 2) =
                __nv_bfloat162(__float2bfloat16(zv[2]), __float2bfloat16(zv[3]));
#pragma unroll
            for (int j = 0; j < 4; j++)
                klsum += 1.f + lv[j] - mu[j] * mu[j] - sg[j] * sg[j];
        }
    }

    if (MODE == 0) {
        __shared__ float sred[256];
        sred[tid] = klsum; __syncthreads();
        for (int s = 128; s > 0; s >>= 1) {
            if (tid < s) sred[tid] += sred[tid + s];
            __syncthreads();
        }
        if (tid == 0) klpart[blockIdx.y * 4 + blockIdx.x] = sred[0];
    }
}

// ====== WMMA bf16 loss: triangular 1-D grid, 128x128 tiles ======
__global__ void __launch_bounds__(256, 2) loss_mma_kernel(
    const __nv_bfloat16* __restrict__ zhi,
    const float* __restrict__ ADJ, float* __restrict__ glpart) {
    int tid = threadIdx.x;
    int idx = blockIdx.x;
    int bi = (int)((129.0 - sqrt(129.0 * 129.0 - 8.0 * idx)) * 0.5);
    while (bi * 64 - bi * (bi - 1) / 2 > idx) bi--;
    while ((bi + 1) * 64 - (bi + 1) * bi / 2 <= idx) bi++;
    int bj = bi + (idx - (bi * 64 - bi * (bi - 1) / 2));
    int rowBase = bi * 128, colBase = bj * 128;

    extern __shared__ __align__(16) char smc[];
    __nv_bfloat16* AH = (__nv_bfloat16*)smc;
    __nv_bfloat16* BH = AH + 128 * LDA;

    int wid = tid >> 5;
    int wm0 = (wid >> 1) * 32;
    int wn0 = (wid & 1) * 64;

    wmma::fragment<wmma::accumulator, 16, 16, 16, float> acc[2][4];
#pragma unroll
    for (int m = 0; m < 2; m++)
#pragma unroll
        for (int n = 0; n < 4; n++) wmma::fill_fragment(acc[m][n], 0.f);

    for (int kc = 0; kc < 2; kc++) {
        int kg = kc * 128;
        for (int i2 = tid; i2 < 128 * 16; i2 += 256) {
            int r = i2 >> 4, c8 = (i2 & 15) << 3;
            *(uint4*)&AH[r * LDA + c8] =
                *(const uint4*)(zhi + (size_t)(rowBase + r) * 256 + kg + c8);
            *(uint4*)&BH[r * LDA + c8] =
                *(const uint4*)(zhi + (size_t)(colBase + r) * 256 + kg + c8);
        }
        __syncthreads();
#pragma unroll
        for (int ks = 0; ks < 8; ks++) {
            int k0 = ks * 16;
            wmma::fragment<wmma::matrix_a, 16, 16, 16, __nv_bfloat16, wmma::row_major> aH[2];
#pragma unroll
            for (int m = 0; m < 2; m++)
                wmma::load_matrix_sync(aH[m], &AH[(wm0 + m * 16) * LDA + k0], LDA);
#pragma unroll
            for (int n = 0; n < 4; n++) {
                wmma::fragment<wmma::matrix_b, 16, 16, 16, __nv_bfloat16, wmma::col_major> bH;
                wmma::load_matrix_sync(bH, &BH[(wn0 + n * 16) * LDA + k0], LDA);
#pragma unroll
                for (int m = 0; m < 2; m++)
                    wmma::mma_sync(acc[m][n], aH[m], bH, acc[m][n]);
            }
        }
        __syncthreads();
    }

    float* Cs = (float*)smc;
#pragma unroll
    for (int m = 0; m < 2; m++)
#pragma unroll
        for (int n = 0; n < 4; n++)
            wmma::store_matrix_sync(&Cs[(wm0 + m * 16) * LDC2 + wn0 + n * 16],
                                    acc[m][n], LDC2, wmma::mem_row_major);
    __syncthreads();

    float term = 0.f;
    bool offdiag = (bi != bj);
    {
        int jl4 = (tid & 31) << 2;
        int j0 = colBase + jl4;
        for (int il = tid >> 5; il < 128; il += 8) {
            int i = rowBase + il;
            float4 c4 = *(float4*)&Cs[il * LDC2 + jl4];
            float4 a4 = *(const float4*)(ADJ + (size_t)i * NN + j0);
            float cs[4] = {c4.x, c4.y, c4.z, c4.w};
            float as[4] = {a4.x, a4.y, a4.z, a4.w};
            if (offdiag || i < j0) {
#pragma unroll
                for (int t = 0; t < 4; t++) {
                    float c = cs[t];
                    float sp = fmaxf(c, 0.f) + __logf(1.f + __expf(-fabsf(c)));
                    term += 2.f * sp - c * as[t];
                }
            } else {
#pragma unroll
                for (int t = 0; t < 4; t++) {
                    int j = j0 + t;
                    if (i > j) continue;
                    float c = cs[t];
                    float sp = fmaxf(c, 0.f) + __logf(1.f + __expf(-fabsf(c)));
                    term += (i < j ? 2.f : 1.f) * sp - c * as[t];
                }
            }
        }
    }
    {
        int il4 = (tid & 31) << 2;
        int i0 = rowBase + il4;
        for (int jl = tid >> 5; jl < 128; jl += 8) {
            int j = colBase + jl;
            float4 a4 = *(const float4*)(ADJ + (size_t)j * NN + i0);
            float as[4] = {a4.x, a4.y, a4.z, a4.w};
            if (offdiag || i0 + 3 < j) {
#pragma unroll
                for (int t = 0; t < 4; t++)
                    term -= Cs[(il4 + t) * LDC2 + jl] * as[t];
            } else {
#pragma unroll
                for (int t = 0; t < 4; t++)
                    if (i0 + t < j)
                        term -= Cs[(il4 + t) * LDC2 + jl] * as[t];
            }
        }
    }

    __shared__ float sred[256];
    sred[tid] = term; __syncthreads();
    for (int s = 128; s > 0; s >>= 1) {
        if (tid < s) sred[tid] += sred[tid + s];
        __syncthreads();
    }
    if (tid == 0) glpart[blockIdx.x] = sred[0];
}

// ================= final reduction =================
__global__ void finalize_kernel(const float* __restrict__ klpart,
                                const float* __restrict__ glpart,
                                float* __restrict__ outScalar) {
    __shared__ double sk[256], sg[256];
    int t = threadIdx.x;
    double a = (double)klpart[t];
    double b = 0.0;
    for (int i = t; i < NLOSS; i += 256) b += (double)glpart[i];
    sk[t] = a; sg[t] = b; __syncthreads();
    for (int s = 128; s > 0; s >>= 1) {
        if (t < s) { sk[t] += sk[t + s]; sg[t] += sg[t + s]; }
        __syncthreads();
    }
    if (t == 0) {
        double kl = -0.5 * sk[0] / (double)NN;
        double gl = sg[0] / ((double)NN * (double)NN);
        *outScalar = (float)(kl + gl);
    }
}

// ================= host launcher =================
extern "C" void kernel_launch(void* const* d_in, const int* in_sizes, int n_in,
                              void* d_out, int out_size) {
    const float* enc = (const float*)d_in[0];
    const int*   ei  = (const int*)d_in[1];
    const float* w   = (const float*)d_in[2];
    const float* ADJ = (const float*)d_in[3];
    const float* eps = (const float*)d_in[4];
    const float* W1 = (const float*)d_in[5];  const float* b1 = (const float*)d_in[6];
    const float* W2 = (const float*)d_in[7];  const float* b2 = (const float*)d_in[8];
    const float* W3 = (const float*)d_in[9];  const float* b3 = (const float*)d_in[10];
    const float* W4 = (const float*)d_in[11]; const float* b4 = (const float*)d_in[12];

    float* out  = (float*)d_out;
    float* enc2 = out;
    float* zreg = out + (size_t)NN * DD;

    int*   deg  = (int*)  (zreg + S_DEG);
    int*   off  = (int*)  (zreg + S_OFF);
    int*   cur  = (int*)  (zreg + S_CUR);
    int*   esrc = (int*)  (zreg + S_ESRC);
    float* ew   =          zreg + S_EW;
    __nv_bfloat16* wsp = (__nv_bfloat16*)(zreg + S_WSP);
    __nv_bfloat16* zhi = (__nv_bfloat16*)(zreg + S_ZLH);
    float* klp  =          zreg + S_KLP;
    float* glp  =          zreg + S_GLP;
    __nv_bfloat16* hch = (__nv_bfloat16*)(zreg + S_HCH);
    __nv_bfloat16* hcl = (__nv_bfloat16*)(zreg + S_HCL);
    float* h1   =          zreg + S_H1;
    float* outScalar = out + (size_t)out_size - 1;

    cudaFuncSetAttribute(loss_mma_kernel,
                         cudaFuncAttributeMaxDynamicSharedMemorySize, LOSS_SMEM);
    cudaFuncSetAttribute(gemm_bf16<true, false, 512>,
                         cudaFuncAttributeMaxDynamicSharedMemorySize, GW_SMEM);
    cudaFuncSetAttribute(gemm_bf16<true, true, 512>,
                         cudaFuncAttributeMaxDynamicSharedMemorySize, GW_SMEM);
    cudaFuncSetAttribute(heads_wmma<0>,
                         cudaFuncAttributeMaxDynamicSharedMemorySize, HD_SMEM);
    cudaFuncSetAttribute(heads_wmma<1>,
                         cudaFuncAttributeMaxDynamicSharedMemorySize, HD_SMEM);

    // weight pre-split + deg zero (fused), then CSR build (1 edge/thread)
    split_w_all<<<384, 256>>>(W1, W2, W3, W4, wsp, deg);
    hist_kernel<<<EE / 256, 256>>>(ei, deg);
    scan_kernel<<<1, 256>>>(deg, off, cur);
    fill_kernel<<<EE / 256, 256>>>(ei, w, cur, esrc, ew);

    // conv1 + linear1 + relu
    gather_kernel<<<NN, 256>>>(enc, hch, hcl, deg, off, esrc, ew);
    gemm_bf16<true, false, 512><<<dim3(2, 64), 256, GW_SMEM>>>(
        hch, hcl, wsp + W1H, wsp + W1L, b1, nullptr, h1);

    // conv2 + linear2 + relu + residual -> enc2
    gather_kernel<<<NN, 256>>>(h1, hch, hcl, deg, off, esrc, ew);
    gemm_bf16<true, true, 512><<<dim3(2, 64), 256, GW_SMEM>>>(
        hch, hcl, wsp + W2H, wsp + W2L, b2, enc, enc2);

    // heads: dual GEMM -> Zl + KL partials + Z for non-protected rows
    heads_wmma<0><<<dim3(4, 64), 256, HD_SMEM>>>(
        enc2, nullptr, nullptr,
        wsp + W3H, wsp + W3L, wsp + W4H, wsp + W4L,
        b3, b4, eps, zreg, zhi, klp);

    // loss GEMM + BCE (triangular 1-D grid)
    loss_mma_kernel<<<NLOSS, 256, LOSS_SMEM>>>(zhi, ADJ, glp);

    // loss scalar (reads klp/glp before cleanup overwrites them)
    finalize_kernel<<<1, 256>>>(klp, glp, outScalar);

    // cleanup: write Z for the 6 protected row-blocks (self-splitting W)
    heads_wmma<1><<<dim3(4, 6), 256, HD_SMEM>>>(
        enc2, W3, W4,
        nullptr, nullptr, nullptr, nullptr,
        b3, b4, eps, zreg, nullptr, nullptr);
}